// round 8
// baseline (speedup 1.0000x reference)
#include <cuda_runtime.h>
#include <math.h>
#include <stdint.h>

// Problem dims (fixed by the dataset)
#define NB 64
#define NO 1024
#define NI 1024
#define OT 4                      // o-rows per block (mu/sigma staged in smem)
#define BT 32                     // b-rows per block
#define MAIN_BLOCKS ((NO/OT) * (NB/BT))   // 256 * 2 = 512

// Scratch (no allocations allowed -> __device__ globals)
__device__ double g_part[MAIN_BLOCKS][5];
__device__ int    g_counter;   // zero-init; reset by last block each run

// ---- packed f32x2 helpers (Blackwell FFMA2 path, PTX-only) ------------------
__device__ __forceinline__ unsigned long long f2_fma(unsigned long long a,
                                                     unsigned long long b,
                                                     unsigned long long c) {
    unsigned long long d;
    asm("fma.rn.f32x2 %0, %1, %2, %3;" : "=l"(d) : "l"(a), "l"(b), "l"(c));
    return d;
}
__device__ __forceinline__ unsigned long long f2_mul(unsigned long long a,
                                                     unsigned long long b) {
    unsigned long long d;
    asm("mul.rn.f32x2 %0, %1, %2;" : "=l"(d) : "l"(a), "l"(b));
    return d;
}
__device__ __forceinline__ unsigned long long f2_add(unsigned long long a,
                                                     unsigned long long b) {
    unsigned long long d;
    asm("add.rn.f32x2 %0, %1, %2;" : "=l"(d) : "l"(a), "l"(b));
    return d;
}
__device__ __forceinline__ unsigned long long f2_pack(float lo, float hi) {
    unsigned long long d;
    asm("mov.b64 %0, {%1, %2};" : "=l"(d) : "f"(lo), "f"(hi));
    return d;
}
__device__ __forceinline__ void f2_unpack(unsigned long long v, float& lo, float& hi) {
    asm("mov.b64 {%0, %1}, %2;" : "=f"(lo), "=f"(hi) : "l"(v));
}
__device__ __forceinline__ float ex2a(float x) {
    float y; asm("ex2.approx.f32 %0, %1;" : "=f"(y) : "f"(x)); return y;
}

// ---------------------------------------------------------------------------
// Main kernel: fused softplus(rho) + GEMV + prior/posterior stats + finalize
// block: 256 threads = 8 warps; tile = OT o-rows x BT b-rows.
// grid=512 with occ 3 (85-reg budget): 148 SMs x 3 blocks = 444 slots, so the
// wave actually delivers ~24 warps/SM -> ~96 outstanding eps loads per SM.
// ---------------------------------------------------------------------------
__global__ __launch_bounds__(256, 3) void main_kernel(
    const float* __restrict__ x,
    const float* __restrict__ wmu,
    const float* __restrict__ wrho,
    const float* __restrict__ bmu,
    const float* __restrict__ brho,
    const float* __restrict__ epsw,
    const float* __restrict__ epsb,
    float* __restrict__ out)
{
    __shared__ float  mu_s[OT * NI];   // 16KB
    __shared__ float  sg_s[OT * NI];   // 16KB
    __shared__ float  red[256];
    __shared__ double dred[256];
    __shared__ int    is_last;

    const float KP   = 6.2146080984221914f;   // -log(0.002)
    const float C2   = 124999.5f;             // 1/(2*0.002^2) - 0.5
    const float NC2L = -180336.15876359287f;  // -C2 * log2(e)
    const float KPL2 = 8.96578433024671f;     // KP * log2(e)
    const unsigned long long NC2L2 = f2_pack(NC2L, NC2L);
    const unsigned long long KPL22 = f2_pack(KPL2, KPL2);
    const unsigned long long ONE2  = f2_pack(1.f, 1.f);

    int t      = threadIdx.x;
    int ot     = blockIdx.x & ((NO / OT) - 1);   // 0..255
    int bh     = blockIdx.x >> 8;                // 0..1
    int o_base = ot * OT;
    int b_base = bh * BT;

    // stage mu and sigma=softplus(rho) into smem, accumulating sum(log sigma)
    float lsig = 0.f;
#pragma unroll
    for (int k = 0; k < 4; k++) {
        int f   = t + k * 256;
        int row = f >> 8;
        int col = (f & 255) << 2;
        float4 m = *reinterpret_cast<const float4*>(wmu + (size_t)(o_base + row) * NI + col);
        float4 r = *reinterpret_cast<const float4*>(wrho + (size_t)(o_base + row) * NI + col);
        float4 s;
        s.x = log1pf(__expf(r.x));
        s.y = log1pf(__expf(r.y));
        s.z = log1pf(__expf(r.z));
        s.w = log1pf(__expf(r.w));
        lsig += __logf(s.x) + __logf(s.y) + __logf(s.z) + __logf(s.w);
        *reinterpret_cast<float4*>(&mu_s[row * NI + col]) = m;
        *reinterpret_cast<float4*>(&sg_s[row * NI + col]) = s;
    }
    __syncthreads();

    int warp = t >> 5, lane = t & 31;

    // single packed accumulator chains (reg-lean; dep chains hidden by mem lat)
    unsigned long long stA = 0ull;   // sum w^2
    unsigned long long seA = 0ull;   // sum eps^2
    float sr = 0.f;                  // sum softplus(df)
    float pb = 0.f;                  // bias posterior extras
    float st_bias = 0.f;             // bias w^2 (scalar, tiny)

    // per element-pair: w=fma(s,e,m); d+=w*x; se+=e*e; t=w*w; st+=t;
    // u=fma(t,-C2*l2e,KP*l2e); p=p*(1+2^u) -> softplus product trick
    // (df <= 6.2146 => factor <= 501; 8 factors/slot/j => <= 4.1e21, safe)
#define BODY2(E2, M2, S2, X2, DI)                                 \
    {                                                             \
        unsigned long long w2 = f2_fma((S2), (E2), (M2));         \
        d2[DI] = f2_fma(w2, (X2), d2[DI]);                        \
        seA    = f2_fma((E2), (E2), seA);                         \
        unsigned long long t2 = f2_mul(w2, w2);                   \
        stA = f2_add(stA, t2);                                    \
        unsigned long long u2 = f2_fma(t2, NC2L2, KPL22);         \
        float ul, uh; f2_unpack(u2, ul, uh);                      \
        unsigned long long ee = f2_pack(ex2a(ul), ex2a(uh));      \
        pA = f2_fma(pA, ee, pA);                                  \
    }

    for (int bb = 0; bb < 4; bb++) {
        int b = b_base + warp + bb * 8;
        unsigned long long d2[OT];
#pragma unroll
        for (int oi = 0; oi < OT; oi++) d2[oi] = 0ull;

        const float* xrow = x + (size_t)b * NI;
        const float* erow = epsw + (((size_t)(b * NO + o_base)) << 10);

        for (int j = 0; j < 8; j++) {
            int bi = (j << 7) + (lane << 2);
            ulonglong2 xv = *reinterpret_cast<const ulonglong2*>(xrow + bi);

            unsigned long long pA = ONE2;   // 8 factors per slot this j
#pragma unroll
            for (int oi = 0; oi < OT; oi++) {
                ulonglong2 e = *reinterpret_cast<const ulonglong2*>(erow + (size_t)oi * NI + bi);
                ulonglong2 m = *reinterpret_cast<const ulonglong2*>(&mu_s[oi * NI + bi]);
                ulonglong2 s = *reinterpret_cast<const ulonglong2*>(&sg_s[oi * NI + bi]);
                BODY2(e.x, m.x, s.x, xv.x, oi)
                BODY2(e.y, m.y, s.y, xv.y, oi)
            }
            float al, ah;
            f2_unpack(pA, al, ah);
            sr += __logf(al) + __logf(ah);   // args <= 501^8, no overflow
        }

        // reduce dots, add sampled bias, emit out[b,o]; lane0 folds bias stats
#pragma unroll
        for (int oi = 0; oi < OT; oi++) {
            float vl, vh;
            f2_unpack(d2[oi], vl, vh);
            float v = vl + vh;
#pragma unroll
            for (int off = 16; off; off >>= 1)
                v += __shfl_down_sync(0xffffffffu, v, off);
            if (lane == 0) {
                int o    = o_base + oi;
                float bs = log1pf(expf(brho[o]));          // softplus(bias_rho)
                float eb = epsb[b * NO + o];
                float bv = fmaf(bs, eb, bmu[o]);           // sampled bias
                out[b * NO + o] = v + bv;
                pb += -logf(bs) - 0.5f * eb * eb;          // bias posterior
                float tb = bv * bv;                        // bias prior
                st_bias += tb;
                float dfb = fmaf(tb, -C2, KP);
                sr += fmaxf(dfb, 0.f);
                float fdb = fabsf(dfb);
                if (fdb < 15.f) sr += log1pf(expf(-fdb));
            }
        }
    }
#undef BODY2

    // collapse packed accumulators to scalars
    float s0l, s0h, s1l, s1h;
    f2_unpack(stA, s0l, s0h);
    f2_unpack(seA, s1l, s1h);
    float st = s0l + s0h + st_bias;
    float se = s1l + s1h;

    // block reduction of the 5 accumulators -> deterministic double partials
    float acc[5] = {st, sr, se, pb, lsig};
#pragma unroll
    for (int q = 0; q < 5; q++) {
        __syncthreads();
        red[t] = acc[q];
        __syncthreads();
        for (int s = 128; s > 0; s >>= 1) {
            if (t < s) red[t] += red[t + s];
            __syncthreads();
        }
        if (t == 0) g_part[blockIdx.x][q] = (double)red[0];
    }

    // ---- last-block finalize (deterministic fixed-order double reduction) ----
    __threadfence();
    if (t == 0) {
        int old = atomicAdd(&g_counter, 1);
        is_last = (old == MAIN_BLOCKS - 1) ? 1 : 0;
    }
    __syncthreads();
    if (!is_last) return;
    __threadfence();

    double a[5] = {0, 0, 0, 0, 0};
    for (int i = t; i < MAIN_BLOCKS; i += 256)
#pragma unroll
        for (int q = 0; q < 5; q++) a[q] += g_part[i][q];

    double tot[5];
#pragma unroll
    for (int q = 0; q < 5; q++) {
        __syncthreads();
        dred[t] = a[q];
        __syncthreads();
        for (int s = 128; s > 0; s >>= 1) {
            if (t < s) dred[t] += dred[t + s];
            __syncthreads();
        }
        tot[q] = dred[0];
    }
    if (t == 0) {
        const double c   = 0.9189385332046727;     // log(sqrt(2*pi))
        const double l05 = -0.6931471805599453;    // log(0.5)
        const double Nw  = 67108864.0;             // B*O*I
        const double Nb2 = 65536.0;                // B*O
        double lp    = (Nw + Nb2) * (l05 - c) - 0.5 * tot[0] + tot[1];
        // lsig counted twice (bh=0 and bh=1 both stage it) -> 64/2 = 32
        double lpost = -(Nw + Nb2) * c - 32.0 * tot[4] - 0.5 * tot[2] + tot[3];
        out[NB * NO]     = (float)lp;
        out[NB * NO + 1] = (float)lpost;
        g_counter = 0;                              // reset for next graph replay
    }
}

// ---------------------------------------------------------------------------
extern "C" void kernel_launch(void* const* d_in, const int* in_sizes, int n_in,
                              void* d_out, int out_size)
{
    const float* x    = (const float*)d_in[0];   // (64,1024)
    const float* wmu  = (const float*)d_in[1];   // (1024,1024)
    const float* wrho = (const float*)d_in[2];   // (1024,1024)
    const float* bmu  = (const float*)d_in[3];   // (1024,)
    const float* brho = (const float*)d_in[4];   // (1024,)
    const float* epsw = (const float*)d_in[5];   // (64,1024,1024)
    const float* epsb = (const float*)d_in[6];   // (64,1024)
    float* out = (float*)d_out;                  // 65536 + 2

    main_kernel<<<MAIN_BLOCKS, 256>>>(x, wmu, wrho, bmu, brho, epsw, epsb, out);
}

// round 9
// speedup vs baseline: 1.3524x; 1.3524x over previous
#include <cuda_runtime.h>
#include <math.h>
#include <stdint.h>

// Problem dims (fixed by the dataset)
#define NB 64
#define NO 1024
#define NI 1024
#define OT 4                      // o-rows per block (mu/sigma staged in smem)
#define MAIN_BLOCKS (NO/OT)       // 256: one block covers all 64 batch rows

// Scratch (no allocations allowed -> __device__ globals)
__device__ double g_part[MAIN_BLOCKS][5];
__device__ int    g_counter;   // zero-init; reset by last block each run

// ---- packed f32x2 helpers (Blackwell FFMA2 path, PTX-only) ------------------
__device__ __forceinline__ unsigned long long f2_fma(unsigned long long a,
                                                     unsigned long long b,
                                                     unsigned long long c) {
    unsigned long long d;
    asm("fma.rn.f32x2 %0, %1, %2, %3;" : "=l"(d) : "l"(a), "l"(b), "l"(c));
    return d;
}
__device__ __forceinline__ unsigned long long f2_mul(unsigned long long a,
                                                     unsigned long long b) {
    unsigned long long d;
    asm("mul.rn.f32x2 %0, %1, %2;" : "=l"(d) : "l"(a), "l"(b));
    return d;
}
__device__ __forceinline__ unsigned long long f2_add(unsigned long long a,
                                                     unsigned long long b) {
    unsigned long long d;
    asm("add.rn.f32x2 %0, %1, %2;" : "=l"(d) : "l"(a), "l"(b));
    return d;
}
__device__ __forceinline__ unsigned long long f2_pack(float lo, float hi) {
    unsigned long long d;
    asm("mov.b64 %0, {%1, %2};" : "=l"(d) : "f"(lo), "f"(hi));
    return d;
}
__device__ __forceinline__ void f2_unpack(unsigned long long v, float& lo, float& hi) {
    asm("mov.b64 {%0, %1}, %2;" : "=f"(lo), "=f"(hi) : "l"(v));
}
__device__ __forceinline__ float ex2a(float x) {
    float y; asm("ex2.approx.f32 %0, %1;" : "=f"(y) : "f"(x)); return y;
}

// ---------------------------------------------------------------------------
// Main kernel: fused softplus(rho) + GEMV + prior/posterior stats + finalize
// block: 256 threads = 8 warps; tile = OT o-rows x ALL 64 b-rows.
// Each warp streams TWO b-rows per j-step (8 eps LDG.128 in flight/warp)
// -> ~128 lines outstanding per 2-block SM: DRAM latency fully covered.
// ---------------------------------------------------------------------------
__global__ __launch_bounds__(256, 2) void main_kernel(
    const float* __restrict__ x,
    const float* __restrict__ wmu,
    const float* __restrict__ wrho,
    const float* __restrict__ bmu,
    const float* __restrict__ brho,
    const float* __restrict__ epsw,
    const float* __restrict__ epsb,
    float* __restrict__ out)
{
    __shared__ float  mu_s[OT * NI];   // 16KB
    __shared__ float  sg_s[OT * NI];   // 16KB
    __shared__ float  red[256];
    __shared__ double dred[256];
    __shared__ int    is_last;

    const float KP   = 6.2146080984221914f;   // -log(0.002)
    const float C2   = 124999.5f;             // 1/(2*0.002^2) - 0.5
    const float NC2L = -180336.15876359287f;  // -C2 * log2(e)
    const float KPL2 = 8.96578433024671f;     // KP * log2(e)
    const unsigned long long NC2L2 = f2_pack(NC2L, NC2L);
    const unsigned long long KPL22 = f2_pack(KPL2, KPL2);
    const unsigned long long ONE2  = f2_pack(1.f, 1.f);

    int t      = threadIdx.x;
    int o_base = blockIdx.x * OT;

    // stage mu and sigma=softplus(rho) into smem, accumulating sum(log sigma)
    float lsig = 0.f;
#pragma unroll
    for (int k = 0; k < 4; k++) {
        int f   = t + k * 256;
        int row = f >> 8;
        int col = (f & 255) << 2;
        float4 m = *reinterpret_cast<const float4*>(wmu + (size_t)(o_base + row) * NI + col);
        float4 r = *reinterpret_cast<const float4*>(wrho + (size_t)(o_base + row) * NI + col);
        float4 s;
        s.x = log1pf(__expf(r.x));
        s.y = log1pf(__expf(r.y));
        s.z = log1pf(__expf(r.z));
        s.w = log1pf(__expf(r.w));
        lsig += __logf(s.x) + __logf(s.y) + __logf(s.z) + __logf(s.w);
        *reinterpret_cast<float4*>(&mu_s[row * NI + col]) = m;
        *reinterpret_cast<float4*>(&sg_s[row * NI + col]) = s;
    }
    __syncthreads();

    int warp = t >> 5, lane = t & 31;

    // lean accumulator chains (dep chains hidden behind memory latency)
    unsigned long long stA = 0ull;   // sum w^2
    unsigned long long seA = 0ull;   // sum eps^2
    float sr = 0.f;                  // sum softplus(df)
    float pb = 0.f;                  // bias posterior extras
    float st_bias = 0.f;             // bias w^2 (scalar, tiny)

    // per element-pair: w=fma(s,e,m); d+=w*x; se+=e*e; t=w*w; st+=t;
    // u=fma(t,-C2*l2e,KP*l2e); p=p*(1+2^u) -> softplus product trick
    // (df <= 6.2146 => factor <= 501; 8 factors/slot/j/b => <= 4.1e21, safe)
#define BODY2(E2, M2, S2, X2, DACC, PQ)                           \
    {                                                             \
        unsigned long long w2 = f2_fma((S2), (E2), (M2));         \
        DACC   = f2_fma(w2, (X2), DACC);                          \
        seA    = f2_fma((E2), (E2), seA);                         \
        unsigned long long t2 = f2_mul(w2, w2);                   \
        stA = f2_add(stA, t2);                                    \
        unsigned long long u2 = f2_fma(t2, NC2L2, KPL22);         \
        float ul, uh; f2_unpack(u2, ul, uh);                      \
        unsigned long long ee = f2_pack(ex2a(ul), ex2a(uh));      \
        PQ = f2_fma(PQ, ee, PQ);                                  \
    }

    for (int bb = 0; bb < 4; bb++) {
        int bA = bb * 16 + warp;       // two b-rows per warp per pass
        int bB = bA + 8;

        unsigned long long dA[OT], dB[OT];
#pragma unroll
        for (int oi = 0; oi < OT; oi++) { dA[oi] = 0ull; dB[oi] = 0ull; }

        const float* xrA = x + (size_t)bA * NI;
        const float* xrB = x + (size_t)bB * NI;
        const float* erA = epsw + (((size_t)(bA * NO + o_base)) << 10);
        const float* erB = epsw + (((size_t)(bB * NO + o_base)) << 10);

        for (int j = 0; j < 8; j++) {
            int bi = (j << 7) + (lane << 2);

            // 8 independent eps LDG.128 batched up front -> deep MLP
            ulonglong2 eA[OT], eB[OT];
#pragma unroll
            for (int oi = 0; oi < OT; oi++)
                eA[oi] = *reinterpret_cast<const ulonglong2*>(erA + (size_t)oi * NI + bi);
#pragma unroll
            for (int oi = 0; oi < OT; oi++)
                eB[oi] = *reinterpret_cast<const ulonglong2*>(erB + (size_t)oi * NI + bi);

            ulonglong2 xvA = *reinterpret_cast<const ulonglong2*>(xrA + bi);
            ulonglong2 xvB = *reinterpret_cast<const ulonglong2*>(xrB + bi);

            unsigned long long pA = ONE2, pB = ONE2;   // 8 factors/slot each
#pragma unroll
            for (int oi = 0; oi < OT; oi++) {
                // mu/sigma smem reads shared across both b-rows
                ulonglong2 m = *reinterpret_cast<const ulonglong2*>(&mu_s[oi * NI + bi]);
                ulonglong2 s = *reinterpret_cast<const ulonglong2*>(&sg_s[oi * NI + bi]);
                BODY2(eA[oi].x, m.x, s.x, xvA.x, dA[oi], pA)
                BODY2(eA[oi].y, m.y, s.y, xvA.y, dA[oi], pA)
                BODY2(eB[oi].x, m.x, s.x, xvB.x, dB[oi], pB)
                BODY2(eB[oi].y, m.y, s.y, xvB.y, dB[oi], pB)
            }
            float al, ah, bl, bh2;
            f2_unpack(pA, al, ah);
            f2_unpack(pB, bl, bh2);
            sr += __logf(al) + __logf(ah) + __logf(bl) + __logf(bh2);
        }

        // reduce dots, add sampled bias, emit out[b,o]; lane0 folds bias stats
#pragma unroll
        for (int oi = 0; oi < OT; oi++) {
#pragma unroll
            for (int half = 0; half < 2; half++) {
                int b = half ? bB : bA;
                float vl, vh;
                f2_unpack(half ? dB[oi] : dA[oi], vl, vh);
                float v = vl + vh;
#pragma unroll
                for (int off = 16; off; off >>= 1)
                    v += __shfl_down_sync(0xffffffffu, v, off);
                if (lane == 0) {
                    int o    = o_base + oi;
                    float bs = log1pf(expf(brho[o]));          // softplus(bias_rho)
                    float eb = epsb[b * NO + o];
                    float bv = fmaf(bs, eb, bmu[o]);           // sampled bias
                    out[b * NO + o] = v + bv;
                    pb += -logf(bs) - 0.5f * eb * eb;          // bias posterior
                    float tb = bv * bv;                        // bias prior
                    st_bias += tb;
                    float dfb = fmaf(tb, -C2, KP);
                    sr += fmaxf(dfb, 0.f);
                    float fdb = fabsf(dfb);
                    if (fdb < 15.f) sr += log1pf(expf(-fdb));
                }
            }
        }
    }
#undef BODY2

    // collapse packed accumulators to scalars
    float s0l, s0h, s1l, s1h;
    f2_unpack(stA, s0l, s0h);
    f2_unpack(seA, s1l, s1h);
    float st = s0l + s0h + st_bias;
    float se = s1l + s1h;

    // block reduction of the 5 accumulators -> deterministic double partials
    float acc[5] = {st, sr, se, pb, lsig};
#pragma unroll
    for (int q = 0; q < 5; q++) {
        __syncthreads();
        red[t] = acc[q];
        __syncthreads();
        for (int s = 128; s > 0; s >>= 1) {
            if (t < s) red[t] += red[t + s];
            __syncthreads();
        }
        if (t == 0) g_part[blockIdx.x][q] = (double)red[0];
    }

    // ---- last-block finalize (deterministic fixed-order double reduction) ----
    __threadfence();
    if (t == 0) {
        int old = atomicAdd(&g_counter, 1);
        is_last = (old == MAIN_BLOCKS - 1) ? 1 : 0;
    }
    __syncthreads();
    if (!is_last) return;
    __threadfence();

    double a[5] = {0, 0, 0, 0, 0};
    for (int i = t; i < MAIN_BLOCKS; i += 256)
#pragma unroll
        for (int q = 0; q < 5; q++) a[q] += g_part[i][q];

    double tot[5];
#pragma unroll
    for (int q = 0; q < 5; q++) {
        __syncthreads();
        dred[t] = a[q];
        __syncthreads();
        for (int s = 128; s > 0; s >>= 1) {
            if (t < s) dred[t] += dred[t + s];
            __syncthreads();
        }
        tot[q] = dred[0];
    }
    if (t == 0) {
        const double c   = 0.9189385332046727;     // log(sqrt(2*pi))
        const double l05 = -0.6931471805599453;    // log(0.5)
        const double Nw  = 67108864.0;             // B*O*I
        const double Nb2 = 65536.0;                // B*O
        double lp    = (Nw + Nb2) * (l05 - c) - 0.5 * tot[0] + tot[1];
        // each o-tile staged exactly once -> coefficient B = 64
        double lpost = -(Nw + Nb2) * c - 64.0 * tot[4] - 0.5 * tot[2] + tot[3];
        out[NB * NO]     = (float)lp;
        out[NB * NO + 1] = (float)lpost;
        g_counter = 0;                              // reset for next graph replay
    }
}

// ---------------------------------------------------------------------------
extern "C" void kernel_launch(void* const* d_in, const int* in_sizes, int n_in,
                              void* d_out, int out_size)
{
    const float* x    = (const float*)d_in[0];   // (64,1024)
    const float* wmu  = (const float*)d_in[1];   // (1024,1024)
    const float* wrho = (const float*)d_in[2];   // (1024,1024)
    const float* bmu  = (const float*)d_in[3];   // (1024,)
    const float* brho = (const float*)d_in[4];   // (1024,)
    const float* epsw = (const float*)d_in[5];   // (64,1024,1024)
    const float* epsb = (const float*)d_in[6];   // (64,1024)
    float* out = (float*)d_out;                  // 65536 + 2

    main_kernel<<<MAIN_BLOCKS, 256>>>(x, wmu, wrho, bmu, brho, epsw, epsb, out);
}